// round 1
// baseline (speedup 1.0000x reference)
#include <cuda_runtime.h>
#include <cuda_bf16.h>
#include <cstdint>

#define NPTS   65536
#define NBATCH 128
#define NPOINT 10
#define NSAMPLE 8
#define P_POS  (NBATCH * NPOINT * NSAMPLE)   // 10240
#define SMEM_PTS 57344                        // points whose dist lives in smem (224KB)
#define CAP 768

// ---------------- scratch (device globals; no allocation) ----------------
__device__ float g_new_xyz[NBATCH * NPOINT * 3];
__device__ float g_grouped[NBATCH * NPOINT * NSAMPLE * 3];
__device__ float g_x1[P_POS * 8];
__device__ float g_x2[P_POS * 8];
__device__ float g_x3[P_POS * 16];
__device__ float g_feat[NBATCH * 160];
__device__ float g_h[NBATCH * 128];

// =========================================================================
// K1: Farthest point sampling. One CTA per batch, persistent over 10 iters.
// dist: 57344 pts in dynamic smem + 8192 pts in registers (8/thread).
// xyz re-read from L2 each iteration (whole 100MB set is L2-resident).
// =========================================================================
__global__ __launch_bounds__(1024, 1) void fps_kernel(const float* __restrict__ pc)
{
    extern __shared__ float sdist[];          // SMEM_PTS floats
    __shared__ float s_rv[32];
    __shared__ int   s_rn[32];
    __shared__ float s_c[3];
    __shared__ int   s_far;

    const int b   = blockIdx.x;
    const int tid = threadIdx.x;
    const float* px = pc + (size_t)b * 3u * (size_t)NPTS;
    const float* py = px + NPTS;
    const float* pz = px + 2 * NPTS;

    for (int i = tid; i < SMEM_PTS; i += 1024) sdist[i] = 1e10f;
    float4 r14 = make_float4(1e10f, 1e10f, 1e10f, 1e10f);
    float4 r15 = r14;
    if (tid == 0) s_far = 0;
    __syncthreads();

    for (int it = 0; it < NPOINT; ++it) {
        if (tid == 0) {
            int far = s_far;
            float cx = px[far], cy = py[far], cz = pz[far];
            s_c[0] = cx; s_c[1] = cy; s_c[2] = cz;
            float* nz = g_new_xyz + (b * NPOINT + it) * 3;
            nz[0] = cx; nz[1] = cy; nz[2] = cz;
        }
        __syncthreads();
        const float cx = s_c[0], cy = s_c[1], cz = s_c[2];

        float bestv = -1.0f;
        int   bestn = 0;
        auto upd = [&](float x, float y, float z, float dc, int n) -> float {
            float dx = x - cx, dy = y - cy, dz = z - cz;
            float d  = dx * dx + dy * dy + dz * dz;
            float nd = fminf(dc, d);
            if (nd > bestv) { bestv = nd; bestn = n; }
            return nd;
        };

        #pragma unroll 2
        for (int j = 0; j < 14; ++j) {
            int base = j * 4096 + tid * 4;
            float4 x = *(const float4*)(px + base);
            float4 y = *(const float4*)(py + base);
            float4 z = *(const float4*)(pz + base);
            float4 dc = *(float4*)(sdist + base);
            dc.x = upd(x.x, y.x, z.x, dc.x, base);
            dc.y = upd(x.y, y.y, z.y, dc.y, base + 1);
            dc.z = upd(x.z, y.z, z.z, dc.z, base + 2);
            dc.w = upd(x.w, y.w, z.w, dc.w, base + 3);
            *(float4*)(sdist + base) = dc;
        }
        {
            int base = 57344 + tid * 4;
            float4 x = *(const float4*)(px + base);
            float4 y = *(const float4*)(py + base);
            float4 z = *(const float4*)(pz + base);
            r14.x = upd(x.x, y.x, z.x, r14.x, base);
            r14.y = upd(x.y, y.y, z.y, r14.y, base + 1);
            r14.z = upd(x.z, y.z, z.z, r14.z, base + 2);
            r14.w = upd(x.w, y.w, z.w, r14.w, base + 3);
        }
        {
            int base = 61440 + tid * 4;
            float4 x = *(const float4*)(px + base);
            float4 y = *(const float4*)(py + base);
            float4 z = *(const float4*)(pz + base);
            r15.x = upd(x.x, y.x, z.x, r15.x, base);
            r15.y = upd(x.y, y.y, z.y, r15.y, base + 1);
            r15.z = upd(x.z, y.z, z.z, r15.z, base + 2);
            r15.w = upd(x.w, y.w, z.w, r15.w, base + 3);
        }

        // argmax reduction, tie -> smaller index (matches jnp.argmax first-occurrence)
        #pragma unroll
        for (int off = 16; off > 0; off >>= 1) {
            float ov = __shfl_down_sync(0xffffffffu, bestv, off);
            int   on = __shfl_down_sync(0xffffffffu, bestn, off);
            if (ov > bestv || (ov == bestv && on < bestn)) { bestv = ov; bestn = on; }
        }
        if ((tid & 31) == 0) { s_rv[tid >> 5] = bestv; s_rn[tid >> 5] = bestn; }
        __syncthreads();
        if (tid < 32) {
            bestv = s_rv[tid]; bestn = s_rn[tid];
            #pragma unroll
            for (int off = 16; off > 0; off >>= 1) {
                float ov = __shfl_down_sync(0xffffffffu, bestv, off);
                int   on = __shfl_down_sync(0xffffffffu, bestn, off);
                if (ov > bestv || (ov == bestv && on < bestn)) { bestv = ov; bestn = on; }
            }
            if (tid == 0) s_far = bestn;
        }
        __syncthreads();
    }
}

// =========================================================================
// K2: Ball query + gather + center. One CTA (512 thr) per batch: single pass
// over all points, 10 register-resident centers; hits appended to smem
// lists; then pick 8 smallest indices per center (== sort + take 8 + pad).
// =========================================================================
__global__ __launch_bounds__(512, 1) void ballquery_kernel(const float* __restrict__ pc)
{
    __shared__ float s_cx[NPOINT], s_cy[NPOINT], s_cz[NPOINT], s_sa[NPOINT];
    __shared__ int   s_cnt[NPOINT];
    __shared__ int   s_hits[NPOINT][CAP];
    __shared__ int   s_sel[NPOINT][NSAMPLE];

    const int b   = blockIdx.x;
    const int tid = threadIdx.x;
    const float* px = pc + (size_t)b * 3u * (size_t)NPTS;
    const float* py = px + NPTS;
    const float* pz = px + 2 * NPTS;

    if (tid < NPOINT) {
        const float* nz = g_new_xyz + (b * NPOINT + tid) * 3;
        float cx = nz[0], cy = nz[1], cz = nz[2];
        s_cx[tid] = cx; s_cy[tid] = cy; s_cz[tid] = cz;
        s_sa[tid] = (cx * cx + cy * cy) + cz * cz;     // same form as sum(a*a,-1)
        s_cnt[tid] = 0;
    }
    __syncthreads();

    float rcx[NPOINT], rcy[NPOINT], rcz[NPOINT], rsa[NPOINT];
    #pragma unroll
    for (int c = 0; c < NPOINT; ++c) {
        rcx[c] = s_cx[c]; rcy[c] = s_cy[c]; rcz[c] = s_cz[c]; rsa[c] = s_sa[c];
    }
    const float R2 = 0.04f;

    for (int j = 0; j < 32; ++j) {
        int base = j * 2048 + tid * 4;
        float4 x = *(const float4*)(px + base);
        float4 y = *(const float4*)(py + base);
        float4 z = *(const float4*)(pz + base);
        float xs[4] = {x.x, x.y, x.z, x.w};
        float ys[4] = {y.x, y.y, y.z, y.w};
        float zs[4] = {z.x, z.y, z.z, z.w};
        #pragma unroll
        for (int e = 0; e < 4; ++e) {
            float xe = xs[e], ye = ys[e], ze = zs[e];
            float sb = (xe * xe + ye * ye) + ze * ze;
            #pragma unroll
            for (int c = 0; c < NPOINT; ++c) {
                float dot = rcx[c] * xe + rcy[c] * ye + rcz[c] * ze;
                float sq  = (rsa[c] + sb) - 2.0f * dot;   // reference's expansion form
                if (sq <= R2) {
                    int p = atomicAdd(&s_cnt[c], 1);
                    if (p < CAP) s_hits[c][p] = base + e;
                }
            }
        }
    }
    __syncthreads();

    const int w = tid >> 5, lane = tid & 31;
    if (w < NPOINT) {
        int m = min(s_cnt[w], CAP);
        int prev = -1;
        for (int r = 0; r < NSAMPLE; ++r) {
            int best = 0x7fffffff;
            for (int i = lane; i < m; i += 32) {
                int v = s_hits[w][i];
                if (v > prev && v < best) best = v;
            }
            #pragma unroll
            for (int off = 16; off > 0; off >>= 1)
                best = min(best, __shfl_down_sync(0xffffffffu, best, off));
            best = __shfl_sync(0xffffffffu, best, 0);
            if (lane == 0) s_sel[w][r] = best;
            prev = best;
        }
    }
    __syncthreads();

    if (w < NPOINT && lane < NSAMPLE) {
        int n = s_sel[w][lane];
        if (n == 0x7fffffff) n = s_sel[w][0];   // pad with first neighbor
        float gx = px[n] - s_cx[w];
        float gy = py[n] - s_cy[w];
        float gz = pz[n] - s_cz[w];
        float* o = g_grouped + ((size_t)(b * NPOINT + w) * NSAMPLE + lane) * 3;
        o[0] = gx; o[1] = gy; o[2] = gz;
    }
}

// =========================================================================
// K3: grouped MLP (3->8->8->16, training-mode BN over (0,2,3), relu),
// maxpool over samples, FC head (160->128 BN relu ->25).
// Single 1024-thread block; deterministic fixed-order reductions.
// =========================================================================
__global__ __launch_bounds__(1024, 1) void mlp_kernel(
    const float* __restrict__ w1, const float* __restrict__ b1,
    const float* __restrict__ g1, const float* __restrict__ be1,
    const float* __restrict__ w2, const float* __restrict__ b2,
    const float* __restrict__ g2, const float* __restrict__ be2,
    const float* __restrict__ w3, const float* __restrict__ b3,
    const float* __restrict__ g3, const float* __restrict__ be3,
    const float* __restrict__ fc1_w, const float* __restrict__ fc1_b,
    const float* __restrict__ bn1_g, const float* __restrict__ bn1_b,
    const float* __restrict__ fc2_w, const float* __restrict__ fc2_b,
    float* __restrict__ out)
{
    const int tid  = threadIdx.x;
    const int lane = tid & 31;
    const int warp = tid >> 5;
    const int P    = P_POS;

    __shared__ float s_w[16 * 8];
    __shared__ float s_bias[16], s_g[16], s_be[16];
    __shared__ float s_part[32 * 32];           // [warp][slot]: slot<16 sum, 16+o sq
    __shared__ float s_scale[16], s_shift[16];
    __shared__ float s_fpart[2048];             // fc1 partials: [0:1024) sum, [1024:2048) sq
    __shared__ float s_fscale[128], s_fshift[128];

    // ---------------- stage 1: conv 3->8 ----------------
    if (tid < 24) s_w[tid] = w1[tid];
    if (tid < 8) { s_bias[tid] = b1[tid]; s_g[tid] = g1[tid]; s_be[tid] = be1[tid]; }
    __syncthreads();
    {
        float ls[8], lq[8];
        #pragma unroll
        for (int o = 0; o < 8; ++o) { ls[o] = 0.f; lq[o] = 0.f; }
        for (int p = tid; p < P; p += 1024) {
            const float* v = g_grouped + (size_t)p * 3;
            float v0 = v[0], v1 = v[1], v2 = v[2];
            #pragma unroll
            for (int o = 0; o < 8; ++o) {
                float y = s_w[o * 3] * v0 + s_w[o * 3 + 1] * v1 + s_w[o * 3 + 2] * v2 + s_bias[o];
                g_x1[o * P + p] = y;
                ls[o] += y; lq[o] += y * y;
            }
        }
        #pragma unroll
        for (int o = 0; o < 8; ++o) {
            #pragma unroll
            for (int off = 16; off > 0; off >>= 1) {
                ls[o] += __shfl_down_sync(0xffffffffu, ls[o], off);
                lq[o] += __shfl_down_sync(0xffffffffu, lq[o], off);
            }
        }
        if (lane == 0) {
            #pragma unroll
            for (int o = 0; o < 8; ++o) { s_part[warp * 32 + o] = ls[o]; s_part[warp * 32 + 16 + o] = lq[o]; }
        }
        __syncthreads();
        if (tid < 8) {
            float sum = 0.f, sq = 0.f;
            for (int ww = 0; ww < 32; ++ww) { sum += s_part[ww * 32 + tid]; sq += s_part[ww * 32 + 16 + tid]; }
            float m  = sum / (float)P;
            float vv = sq / (float)P - m * m;
            float sc = rsqrtf(vv + 1e-5f) * s_g[tid];
            s_scale[tid] = sc; s_shift[tid] = s_be[tid] - m * sc;
        }
        __syncthreads();
    }

    // ---------------- stage 2: bn1+relu, conv 8->8 ----------------
    if (tid < 64) s_w[tid] = w2[tid];
    if (tid < 8) { s_bias[tid] = b2[tid]; s_g[tid] = g2[tid]; s_be[tid] = be2[tid]; }
    __syncthreads();
    {
        float ls[8], lq[8];
        #pragma unroll
        for (int o = 0; o < 8; ++o) { ls[o] = 0.f; lq[o] = 0.f; }
        for (int p = tid; p < P; p += 1024) {
            float a[8];
            #pragma unroll
            for (int o = 0; o < 8; ++o) {
                float x = g_x1[o * P + p] * s_scale[o] + s_shift[o];
                a[o] = fmaxf(x, 0.f);
            }
            #pragma unroll
            for (int o2 = 0; o2 < 8; ++o2) {
                float y = s_bias[o2];
                #pragma unroll
                for (int i = 0; i < 8; ++i) y += s_w[o2 * 8 + i] * a[i];
                g_x2[o2 * P + p] = y;
                ls[o2] += y; lq[o2] += y * y;
            }
        }
        #pragma unroll
        for (int o = 0; o < 8; ++o) {
            #pragma unroll
            for (int off = 16; off > 0; off >>= 1) {
                ls[o] += __shfl_down_sync(0xffffffffu, ls[o], off);
                lq[o] += __shfl_down_sync(0xffffffffu, lq[o], off);
            }
        }
        if (lane == 0) {
            #pragma unroll
            for (int o = 0; o < 8; ++o) { s_part[warp * 32 + o] = ls[o]; s_part[warp * 32 + 16 + o] = lq[o]; }
        }
        __syncthreads();
        if (tid < 8) {
            float sum = 0.f, sq = 0.f;
            for (int ww = 0; ww < 32; ++ww) { sum += s_part[ww * 32 + tid]; sq += s_part[ww * 32 + 16 + tid]; }
            float m  = sum / (float)P;
            float vv = sq / (float)P - m * m;
            float sc = rsqrtf(vv + 1e-5f) * s_g[tid];
            s_scale[tid] = sc; s_shift[tid] = s_be[tid] - m * sc;
        }
        __syncthreads();
    }

    // ---------------- stage 3: bn2+relu, conv 8->16 ----------------
    if (tid < 128) s_w[tid] = w3[tid];
    if (tid < 16) { s_bias[tid] = b3[tid]; s_g[tid] = g3[tid]; s_be[tid] = be3[tid]; }
    __syncthreads();
    {
        float ls[16], lq[16];
        #pragma unroll
        for (int o = 0; o < 16; ++o) { ls[o] = 0.f; lq[o] = 0.f; }
        for (int p = tid; p < P; p += 1024) {
            float a[8];
            #pragma unroll
            for (int o = 0; o < 8; ++o) {
                float x = g_x2[o * P + p] * s_scale[o] + s_shift[o];
                a[o] = fmaxf(x, 0.f);
            }
            #pragma unroll
            for (int o2 = 0; o2 < 16; ++o2) {
                float y = s_bias[o2];
                #pragma unroll
                for (int i = 0; i < 8; ++i) y += s_w[o2 * 8 + i] * a[i];
                g_x3[o2 * P + p] = y;
                ls[o2] += y; lq[o2] += y * y;
            }
        }
        #pragma unroll
        for (int o = 0; o < 16; ++o) {
            #pragma unroll
            for (int off = 16; off > 0; off >>= 1) {
                ls[o] += __shfl_down_sync(0xffffffffu, ls[o], off);
                lq[o] += __shfl_down_sync(0xffffffffu, lq[o], off);
            }
        }
        if (lane == 0) {
            #pragma unroll
            for (int o = 0; o < 16; ++o) { s_part[warp * 32 + o] = ls[o]; s_part[warp * 32 + 16 + o] = lq[o]; }
        }
        __syncthreads();
        if (tid < 16) {
            float sum = 0.f, sq = 0.f;
            for (int ww = 0; ww < 32; ++ww) { sum += s_part[ww * 32 + tid]; sq += s_part[ww * 32 + 16 + tid]; }
            float m  = sum / (float)P;
            float vv = sq / (float)P - m * m;
            float sc = rsqrtf(vv + 1e-5f) * s_g[tid];
            s_scale[tid] = sc; s_shift[tid] = s_be[tid] - m * sc;
        }
        __syncthreads();
    }

    // ---------------- stage 4: bn3+relu + maxpool over samples ----------------
    for (int idx = tid; idx < NBATCH * 16 * NPOINT; idx += 1024) {
        int bb  = idx / 160;
        int rem = idx - bb * 160;
        int o   = rem / NPOINT;
        int ctr = rem - o * NPOINT;
        int p0  = (bb * NPOINT + ctr) * NSAMPLE;
        float mx = 0.f;   // relu outputs are >= 0
        #pragma unroll
        for (int k = 0; k < NSAMPLE; ++k) {
            float x = g_x3[o * P + p0 + k] * s_scale[o] + s_shift[o];
            mx = fmaxf(mx, fmaxf(x, 0.f));
        }
        g_feat[bb * 160 + o * NPOINT + ctr] = mx;
    }
    __syncthreads();

    // ---------------- stage 5: fc1 160->128 + batch stats ----------------
    {
        const int j  = tid & 127;
        const int bg = tid >> 7;
        float fs = 0.f, fq = 0.f;
        const float* fw = fc1_w + j * 160;
        float bj = fc1_b[j];
        for (int bb = bg; bb < NBATCH; bb += 8) {
            const float* ft = g_feat + bb * 160;
            float s = bj;
            #pragma unroll 8
            for (int k = 0; k < 160; ++k) s += fw[k] * ft[k];
            g_h[bb * 128 + j] = s;
            fs += s; fq += s * s;
        }
        s_fpart[tid] = fs;
        s_fpart[1024 + tid] = fq;
        __syncthreads();
        if (tid < 128) {
            float sum = 0.f, sq = 0.f;
            for (int g = 0; g < 8; ++g) { sum += s_fpart[g * 128 + tid]; sq += s_fpart[1024 + g * 128 + tid]; }
            float m  = sum / (float)NBATCH;
            float vv = sq / (float)NBATCH - m * m;
            float sc = rsqrtf(vv + 1e-5f) * bn1_g[tid];
            s_fscale[tid] = sc; s_fshift[tid] = bn1_b[tid] - m * sc;
        }
        __syncthreads();
    }

    // ---------------- stage 6: bn+relu, fc2 128->25 ----------------
    for (int i = tid; i < NBATCH * 128; i += 1024) {
        int jj = i & 127;
        float x = g_h[i] * s_fscale[jj] + s_fshift[jj];
        g_h[i] = fmaxf(x, 0.f);
    }
    __syncthreads();
    for (int i = tid; i < NBATCH * 25; i += 1024) {
        int bb = i / 25;
        int o  = i - bb * 25;
        const float* hw = fc2_w + o * 128;
        const float* hh = g_h + bb * 128;
        float s = fc2_b[o];
        #pragma unroll 8
        for (int jj = 0; jj < 128; ++jj) s += hw[jj] * hh[jj];
        out[i] = s;
    }
}

// =========================================================================
extern "C" void kernel_launch(void* const* d_in, const int* in_sizes, int n_in,
                              void* d_out, int out_size)
{
    const float* pc    = (const float*)d_in[0];
    const float* w1    = (const float*)d_in[1];
    const float* b1    = (const float*)d_in[2];
    const float* g1    = (const float*)d_in[3];
    const float* be1   = (const float*)d_in[4];
    const float* w2    = (const float*)d_in[5];
    const float* b2    = (const float*)d_in[6];
    const float* g2    = (const float*)d_in[7];
    const float* be2   = (const float*)d_in[8];
    const float* w3    = (const float*)d_in[9];
    const float* b3    = (const float*)d_in[10];
    const float* g3    = (const float*)d_in[11];
    const float* be3   = (const float*)d_in[12];
    const float* fc1_w = (const float*)d_in[13];
    const float* fc1_b = (const float*)d_in[14];
    const float* bn1_g = (const float*)d_in[15];
    const float* bn1_b = (const float*)d_in[16];
    const float* fc2_w = (const float*)d_in[17];
    const float* fc2_b = (const float*)d_in[18];
    float* out = (float*)d_out;

    static bool attr_set = false;
    (void)attr_set;
    cudaFuncSetAttribute(fps_kernel, cudaFuncAttributeMaxDynamicSharedMemorySize,
                         SMEM_PTS * (int)sizeof(float));

    fps_kernel<<<NBATCH, 1024, SMEM_PTS * sizeof(float)>>>(pc);
    ballquery_kernel<<<NBATCH, 512>>>(pc);
    mlp_kernel<<<1, 1024>>>(w1, b1, g1, be1, w2, b2, g2, be2, w3, b3, g3, be3,
                            fc1_w, fc1_b, bn1_g, bn1_b, fc2_w, fc2_b, out);
}

// round 3
// speedup vs baseline: 4.1911x; 4.1911x over previous
#include <cuda_runtime.h>
#include <cuda_bf16.h>
#include <cstdint>

#define NPTS   65536
#define NBATCH 128
#define NPOINT 10
#define NSAMPLE 8
#define P_POS  (NBATCH * NPOINT * NSAMPLE)   // 10240
#define SMEM_PTS 57344                        // points whose dist lives in smem (224KB)
#define CAP 768

// ---------------- scratch (device globals; no allocation) ----------------
__device__ float g_new_xyz[NBATCH * NPOINT * 3];
__device__ float g_grouped[NBATCH * NPOINT * NSAMPLE * 3];
__device__ float g_x1[P_POS * 8];
__device__ float g_x2[P_POS * 8];
__device__ float g_x3[P_POS * 16];

// =========================================================================
// K1: Farthest point sampling. One CTA per batch, persistent over 10 iters.
// dist: 57344 pts in dynamic smem + 8192 pts in registers (8/thread).
// xyz re-read from L2 each iteration (whole 100MB set ~L2-resident).
// =========================================================================
__global__ __launch_bounds__(1024, 1) void fps_kernel(const float* __restrict__ pc)
{
    extern __shared__ float sdist[];          // SMEM_PTS floats
    __shared__ float s_rv[32];
    __shared__ int   s_rn[32];
    __shared__ float s_c[3];
    __shared__ int   s_far;

    const int b   = blockIdx.x;
    const int tid = threadIdx.x;
    const float* px = pc + (size_t)b * 3u * (size_t)NPTS;
    const float* py = px + NPTS;
    const float* pz = px + 2 * NPTS;

    for (int i = tid; i < SMEM_PTS; i += 1024) sdist[i] = 1e10f;
    float4 r14 = make_float4(1e10f, 1e10f, 1e10f, 1e10f);
    float4 r15 = r14;
    if (tid == 0) s_far = 0;
    __syncthreads();

    for (int it = 0; it < NPOINT; ++it) {
        if (tid == 0) {
            int far = s_far;
            float cx = px[far], cy = py[far], cz = pz[far];
            s_c[0] = cx; s_c[1] = cy; s_c[2] = cz;
            float* nz = g_new_xyz + (b * NPOINT + it) * 3;
            nz[0] = cx; nz[1] = cy; nz[2] = cz;
        }
        __syncthreads();
        const float cx = s_c[0], cy = s_c[1], cz = s_c[2];

        float bestv = -1.0f;
        int   bestn = 0;
        auto upd = [&](float x, float y, float z, float dc, int n) -> float {
            float dx = x - cx, dy = y - cy, dz = z - cz;
            float d  = dx * dx + dy * dy + dz * dz;
            float nd = fminf(dc, d);
            if (nd > bestv) { bestv = nd; bestn = n; }
            return nd;
        };

        #pragma unroll 2
        for (int j = 0; j < 14; ++j) {
            int base = j * 4096 + tid * 4;
            float4 x = *(const float4*)(px + base);
            float4 y = *(const float4*)(py + base);
            float4 z = *(const float4*)(pz + base);
            float4 dc = *(float4*)(sdist + base);
            dc.x = upd(x.x, y.x, z.x, dc.x, base);
            dc.y = upd(x.y, y.y, z.y, dc.y, base + 1);
            dc.z = upd(x.z, y.z, z.z, dc.z, base + 2);
            dc.w = upd(x.w, y.w, z.w, dc.w, base + 3);
            *(float4*)(sdist + base) = dc;
        }
        {
            int base = 57344 + tid * 4;
            float4 x = *(const float4*)(px + base);
            float4 y = *(const float4*)(py + base);
            float4 z = *(const float4*)(pz + base);
            r14.x = upd(x.x, y.x, z.x, r14.x, base);
            r14.y = upd(x.y, y.y, z.y, r14.y, base + 1);
            r14.z = upd(x.z, y.z, z.z, r14.z, base + 2);
            r14.w = upd(x.w, y.w, z.w, r14.w, base + 3);
        }
        {
            int base = 61440 + tid * 4;
            float4 x = *(const float4*)(px + base);
            float4 y = *(const float4*)(py + base);
            float4 z = *(const float4*)(pz + base);
            r15.x = upd(x.x, y.x, z.x, r15.x, base);
            r15.y = upd(x.y, y.y, z.y, r15.y, base + 1);
            r15.z = upd(x.z, y.z, z.z, r15.z, base + 2);
            r15.w = upd(x.w, y.w, z.w, r15.w, base + 3);
        }

        // argmax reduction, tie -> smaller index (matches jnp.argmax first-occurrence)
        #pragma unroll
        for (int off = 16; off > 0; off >>= 1) {
            float ov = __shfl_down_sync(0xffffffffu, bestv, off);
            int   on = __shfl_down_sync(0xffffffffu, bestn, off);
            if (ov > bestv || (ov == bestv && on < bestn)) { bestv = ov; bestn = on; }
        }
        if ((tid & 31) == 0) { s_rv[tid >> 5] = bestv; s_rn[tid >> 5] = bestn; }
        __syncthreads();
        if (tid < 32) {
            bestv = s_rv[tid]; bestn = s_rn[tid];
            #pragma unroll
            for (int off = 16; off > 0; off >>= 1) {
                float ov = __shfl_down_sync(0xffffffffu, bestv, off);
                int   on = __shfl_down_sync(0xffffffffu, bestn, off);
                if (ov > bestv || (ov == bestv && on < bestn)) { bestv = ov; bestn = on; }
            }
            if (tid == 0) s_far = bestn;
        }
        __syncthreads();
    }
}

// =========================================================================
// K2: Ball query + gather + center. One CTA (512 thr) per batch.
// =========================================================================
__global__ __launch_bounds__(512, 1) void ballquery_kernel(const float* __restrict__ pc)
{
    __shared__ float s_cx[NPOINT], s_cy[NPOINT], s_cz[NPOINT], s_sa[NPOINT];
    __shared__ int   s_cnt[NPOINT];
    __shared__ int   s_hits[NPOINT][CAP];
    __shared__ int   s_sel[NPOINT][NSAMPLE];

    const int b   = blockIdx.x;
    const int tid = threadIdx.x;
    const float* px = pc + (size_t)b * 3u * (size_t)NPTS;
    const float* py = px + NPTS;
    const float* pz = px + 2 * NPTS;

    if (tid < NPOINT) {
        const float* nz = g_new_xyz + (b * NPOINT + tid) * 3;
        float cx = nz[0], cy = nz[1], cz = nz[2];
        s_cx[tid] = cx; s_cy[tid] = cy; s_cz[tid] = cz;
        s_sa[tid] = (cx * cx + cy * cy) + cz * cz;
        s_cnt[tid] = 0;
    }
    __syncthreads();

    float rcx[NPOINT], rcy[NPOINT], rcz[NPOINT], rsa[NPOINT];
    #pragma unroll
    for (int c = 0; c < NPOINT; ++c) {
        rcx[c] = s_cx[c]; rcy[c] = s_cy[c]; rcz[c] = s_cz[c]; rsa[c] = s_sa[c];
    }
    const float R2 = 0.04f;

    for (int j = 0; j < 32; ++j) {
        int base = j * 2048 + tid * 4;
        float4 x = *(const float4*)(px + base);
        float4 y = *(const float4*)(py + base);
        float4 z = *(const float4*)(pz + base);
        float xs[4] = {x.x, x.y, x.z, x.w};
        float ys[4] = {y.x, y.y, y.z, y.w};
        float zs[4] = {z.x, z.y, z.z, z.w};
        #pragma unroll
        for (int e = 0; e < 4; ++e) {
            float xe = xs[e], ye = ys[e], ze = zs[e];
            float sb = (xe * xe + ye * ye) + ze * ze;
            #pragma unroll
            for (int c = 0; c < NPOINT; ++c) {
                float dot = rcx[c] * xe + rcy[c] * ye + rcz[c] * ze;
                float sq  = (rsa[c] + sb) - 2.0f * dot;
                if (sq <= R2) {
                    int p = atomicAdd(&s_cnt[c], 1);
                    if (p < CAP) s_hits[c][p] = base + e;
                }
            }
        }
    }
    __syncthreads();

    const int w = tid >> 5, lane = tid & 31;
    if (w < NPOINT) {
        int m = min(s_cnt[w], CAP);
        int prev = -1;
        for (int r = 0; r < NSAMPLE; ++r) {
            int best = 0x7fffffff;
            for (int i = lane; i < m; i += 32) {
                int v = s_hits[w][i];
                if (v > prev && v < best) best = v;
            }
            #pragma unroll
            for (int off = 16; off > 0; off >>= 1)
                best = min(best, __shfl_down_sync(0xffffffffu, best, off));
            best = __shfl_sync(0xffffffffu, best, 0);
            if (lane == 0) s_sel[w][r] = best;
            prev = best;
        }
    }
    __syncthreads();

    if (w < NPOINT && lane < NSAMPLE) {
        int n = s_sel[w][lane];
        if (n == 0x7fffffff) n = s_sel[w][0];
        float gx = px[n] - s_cx[w];
        float gy = py[n] - s_cy[w];
        float gz = pz[n] - s_cz[w];
        float* o = g_grouped + ((size_t)(b * NPOINT + w) * NSAMPLE + lane) * 3;
        o[0] = gx; o[1] = gy; o[2] = gz;
    }
}

// =========================================================================
// K3: grouped MLP + maxpool + FC head. Single 1024-thread block.
// FC stages: warp-per-output-row, lanes split k (all loads coalesced /
// conflict-free), shuffle-tree reduce, deterministic fixed-order stats.
// feat (80KB) and h (64KB) live in dynamic smem (no global round trip).
// =========================================================================
#define FEAT_ELEMS (NBATCH * 160)   // 20480
#define H_ELEMS    (NBATCH * 128)   // 16384

__global__ __launch_bounds__(1024, 1) void mlp_kernel(
    const float* __restrict__ w1, const float* __restrict__ b1,
    const float* __restrict__ g1, const float* __restrict__ be1,
    const float* __restrict__ w2, const float* __restrict__ b2,
    const float* __restrict__ g2, const float* __restrict__ be2,
    const float* __restrict__ w3, const float* __restrict__ b3,
    const float* __restrict__ g3, const float* __restrict__ be3,
    const float* __restrict__ fc1_w, const float* __restrict__ fc1_b,
    const float* __restrict__ bn1_g, const float* __restrict__ bn1_b,
    const float* __restrict__ fc2_w, const float* __restrict__ fc2_b,
    float* __restrict__ out)
{
    extern __shared__ float dsm[];
    float* s_feat = dsm;                 // [NBATCH][160]
    float* s_h    = dsm + FEAT_ELEMS;    // [NBATCH][128]

    const int tid  = threadIdx.x;
    const int lane = tid & 31;
    const int warp = tid >> 5;
    const int P    = P_POS;

    __shared__ float s_w[16 * 8];
    __shared__ float s_bias[16], s_g[16], s_be[16];
    __shared__ float s_part[32 * 32];
    __shared__ float s_scale[16], s_shift[16];
    __shared__ float s_fsum[128], s_fsq[128];
    __shared__ float s_fscale[128], s_fshift[128];

    // ---------------- stage 1: conv 3->8 ----------------
    if (tid < 24) s_w[tid] = w1[tid];
    if (tid < 8) { s_bias[tid] = b1[tid]; s_g[tid] = g1[tid]; s_be[tid] = be1[tid]; }
    __syncthreads();
    {
        float ls[8], lq[8];
        #pragma unroll
        for (int o = 0; o < 8; ++o) { ls[o] = 0.f; lq[o] = 0.f; }
        for (int p = tid; p < P; p += 1024) {
            const float* v = g_grouped + (size_t)p * 3;
            float v0 = v[0], v1 = v[1], v2 = v[2];
            #pragma unroll
            for (int o = 0; o < 8; ++o) {
                float y = s_w[o * 3] * v0 + s_w[o * 3 + 1] * v1 + s_w[o * 3 + 2] * v2 + s_bias[o];
                g_x1[o * P + p] = y;
                ls[o] += y; lq[o] += y * y;
            }
        }
        #pragma unroll
        for (int o = 0; o < 8; ++o) {
            #pragma unroll
            for (int off = 16; off > 0; off >>= 1) {
                ls[o] += __shfl_down_sync(0xffffffffu, ls[o], off);
                lq[o] += __shfl_down_sync(0xffffffffu, lq[o], off);
            }
        }
        if (lane == 0) {
            #pragma unroll
            for (int o = 0; o < 8; ++o) { s_part[warp * 32 + o] = ls[o]; s_part[warp * 32 + 16 + o] = lq[o]; }
        }
        __syncthreads();
        if (tid < 8) {
            float sum = 0.f, sq = 0.f;
            for (int ww = 0; ww < 32; ++ww) { sum += s_part[ww * 32 + tid]; sq += s_part[ww * 32 + 16 + tid]; }
            float m  = sum / (float)P;
            float vv = sq / (float)P - m * m;
            float sc = rsqrtf(vv + 1e-5f) * s_g[tid];
            s_scale[tid] = sc; s_shift[tid] = s_be[tid] - m * sc;
        }
        __syncthreads();
    }

    // ---------------- stage 2: bn1+relu, conv 8->8 ----------------
    if (tid < 64) s_w[tid] = w2[tid];
    if (tid < 8) { s_bias[tid] = b2[tid]; s_g[tid] = g2[tid]; s_be[tid] = be2[tid]; }
    __syncthreads();
    {
        float ls[8], lq[8];
        #pragma unroll
        for (int o = 0; o < 8; ++o) { ls[o] = 0.f; lq[o] = 0.f; }
        for (int p = tid; p < P; p += 1024) {
            float a[8];
            #pragma unroll
            for (int o = 0; o < 8; ++o) {
                float x = g_x1[o * P + p] * s_scale[o] + s_shift[o];
                a[o] = fmaxf(x, 0.f);
            }
            #pragma unroll
            for (int o2 = 0; o2 < 8; ++o2) {
                float y = s_bias[o2];
                #pragma unroll
                for (int i = 0; i < 8; ++i) y += s_w[o2 * 8 + i] * a[i];
                g_x2[o2 * P + p] = y;
                ls[o2] += y; lq[o2] += y * y;
            }
        }
        #pragma unroll
        for (int o = 0; o < 8; ++o) {
            #pragma unroll
            for (int off = 16; off > 0; off >>= 1) {
                ls[o] += __shfl_down_sync(0xffffffffu, ls[o], off);
                lq[o] += __shfl_down_sync(0xffffffffu, lq[o], off);
            }
        }
        if (lane == 0) {
            #pragma unroll
            for (int o = 0; o < 8; ++o) { s_part[warp * 32 + o] = ls[o]; s_part[warp * 32 + 16 + o] = lq[o]; }
        }
        __syncthreads();
        if (tid < 8) {
            float sum = 0.f, sq = 0.f;
            for (int ww = 0; ww < 32; ++ww) { sum += s_part[ww * 32 + tid]; sq += s_part[ww * 32 + 16 + tid]; }
            float m  = sum / (float)P;
            float vv = sq / (float)P - m * m;
            float sc = rsqrtf(vv + 1e-5f) * s_g[tid];
            s_scale[tid] = sc; s_shift[tid] = s_be[tid] - m * sc;
        }
        __syncthreads();
    }

    // ---------------- stage 3: bn2+relu, conv 8->16 ----------------
    if (tid < 128) s_w[tid] = w3[tid];
    if (tid < 16) { s_bias[tid] = b3[tid]; s_g[tid] = g3[tid]; s_be[tid] = be3[tid]; }
    __syncthreads();
    {
        float ls[16], lq[16];
        #pragma unroll
        for (int o = 0; o < 16; ++o) { ls[o] = 0.f; lq[o] = 0.f; }
        for (int p = tid; p < P; p += 1024) {
            float a[8];
            #pragma unroll
            for (int o = 0; o < 8; ++o) {
                float x = g_x2[o * P + p] * s_scale[o] + s_shift[o];
                a[o] = fmaxf(x, 0.f);
            }
            #pragma unroll
            for (int o2 = 0; o2 < 16; ++o2) {
                float y = s_bias[o2];
                #pragma unroll
                for (int i = 0; i < 8; ++i) y += s_w[o2 * 8 + i] * a[i];
                g_x3[o2 * P + p] = y;
                ls[o2] += y; lq[o2] += y * y;
            }
        }
        #pragma unroll
        for (int o = 0; o < 16; ++o) {
            #pragma unroll
            for (int off = 16; off > 0; off >>= 1) {
                ls[o] += __shfl_down_sync(0xffffffffu, ls[o], off);
                lq[o] += __shfl_down_sync(0xffffffffu, lq[o], off);
            }
        }
        if (lane == 0) {
            #pragma unroll
            for (int o = 0; o < 16; ++o) { s_part[warp * 32 + o] = ls[o]; s_part[warp * 32 + 16 + o] = lq[o]; }
        }
        __syncthreads();
        if (tid < 16) {
            float sum = 0.f, sq = 0.f;
            for (int ww = 0; ww < 32; ++ww) { sum += s_part[ww * 32 + tid]; sq += s_part[ww * 32 + 16 + tid]; }
            float m  = sum / (float)P;
            float vv = sq / (float)P - m * m;
            float sc = rsqrtf(vv + 1e-5f) * s_g[tid];
            s_scale[tid] = sc; s_shift[tid] = s_be[tid] - m * sc;
        }
        __syncthreads();
    }

    // ---------------- stage 4: bn3+relu + maxpool over samples -> s_feat ----------------
    for (int idx = tid; idx < NBATCH * 16 * NPOINT; idx += 1024) {
        int bb  = idx / 160;
        int rem = idx - bb * 160;
        int o   = rem / NPOINT;
        int ctr = rem - o * NPOINT;
        int p0  = (bb * NPOINT + ctr) * NSAMPLE;
        float mx = 0.f;   // relu outputs are >= 0
        #pragma unroll
        for (int k = 0; k < NSAMPLE; ++k) {
            float x = g_x3[o * P + p0 + k] * s_scale[o] + s_shift[o];
            mx = fmaxf(mx, fmaxf(x, 0.f));
        }
        s_feat[bb * 160 + o * NPOINT + ctr] = mx;
    }
    __syncthreads();

    // ---------------- stage 5: fc1 160->128, warp-per-j, lanes over k ----------------
    {
        for (int j = warp; j < 128; j += 32) {
            const float* fw = fc1_w + j * 160;
            float fk0 = fw[lane];
            float fk1 = fw[lane + 32];
            float fk2 = fw[lane + 64];
            float fk3 = fw[lane + 96];
            float fk4 = fw[lane + 128];
            float bj  = fc1_b[j];
            float fs = 0.f, fq = 0.f;
            for (int bb = 0; bb < NBATCH; ++bb) {
                const float* ft = s_feat + bb * 160;
                float s = fk0 * ft[lane] + fk1 * ft[lane + 32] + fk2 * ft[lane + 64]
                        + fk3 * ft[lane + 96] + fk4 * ft[lane + 128];
                #pragma unroll
                for (int off = 16; off > 0; off >>= 1)
                    s += __shfl_down_sync(0xffffffffu, s, off);
                if (lane == 0) {
                    s += bj;
                    s_h[bb * 128 + j] = s;
                    fs += s; fq += s * s;
                }
            }
            if (lane == 0) { s_fsum[j] = fs; s_fsq[j] = fq; }
        }
        __syncthreads();
        if (tid < 128) {
            float m  = s_fsum[tid] / (float)NBATCH;
            float vv = s_fsq[tid] / (float)NBATCH - m * m;
            float sc = rsqrtf(vv + 1e-5f) * bn1_g[tid];
            s_fscale[tid] = sc; s_fshift[tid] = bn1_b[tid] - m * sc;
        }
        __syncthreads();
    }

    // ---------------- stage 6: bn+relu in smem, fc2 128->25 warp-per-o ----------------
    for (int i = tid; i < H_ELEMS; i += 1024) {
        int jj = i & 127;
        float x = s_h[i] * s_fscale[jj] + s_fshift[jj];
        s_h[i] = fmaxf(x, 0.f);
    }
    __syncthreads();
    if (warp < 25) {
        const int o = warp;
        const float* hw = fc2_w + o * 128;
        float hk0 = hw[lane];
        float hk1 = hw[lane + 32];
        float hk2 = hw[lane + 64];
        float hk3 = hw[lane + 96];
        float bo  = fc2_b[o];
        for (int bb = 0; bb < NBATCH; ++bb) {
            const float* hh = s_h + bb * 128;
            float s = hk0 * hh[lane] + hk1 * hh[lane + 32]
                    + hk2 * hh[lane + 64] + hk3 * hh[lane + 96];
            #pragma unroll
            for (int off = 16; off > 0; off >>= 1)
                s += __shfl_down_sync(0xffffffffu, s, off);
            if (lane == 0) out[bb * 25 + o] = s + bo;
        }
    }
}

// =========================================================================
extern "C" void kernel_launch(void* const* d_in, const int* in_sizes, int n_in,
                              void* d_out, int out_size)
{
    const float* pc    = (const float*)d_in[0];
    const float* w1    = (const float*)d_in[1];
    const float* b1    = (const float*)d_in[2];
    const float* g1    = (const float*)d_in[3];
    const float* be1   = (const float*)d_in[4];
    const float* w2    = (const float*)d_in[5];
    const float* b2    = (const float*)d_in[6];
    const float* g2    = (const float*)d_in[7];
    const float* be2   = (const float*)d_in[8];
    const float* w3    = (const float*)d_in[9];
    const float* b3    = (const float*)d_in[10];
    const float* g3    = (const float*)d_in[11];
    const float* be3   = (const float*)d_in[12];
    const float* fc1_w = (const float*)d_in[13];
    const float* fc1_b = (const float*)d_in[14];
    const float* bn1_g = (const float*)d_in[15];
    const float* bn1_b = (const float*)d_in[16];
    const float* fc2_w = (const float*)d_in[17];
    const float* fc2_b = (const float*)d_in[18];
    float* out = (float*)d_out;

    cudaFuncSetAttribute(fps_kernel, cudaFuncAttributeMaxDynamicSharedMemorySize,
                         SMEM_PTS * (int)sizeof(float));
    cudaFuncSetAttribute(mlp_kernel, cudaFuncAttributeMaxDynamicSharedMemorySize,
                         (FEAT_ELEMS + H_ELEMS) * (int)sizeof(float));

    fps_kernel<<<NBATCH, 1024, SMEM_PTS * sizeof(float)>>>(pc);
    ballquery_kernel<<<NBATCH, 512>>>(pc);
    mlp_kernel<<<1, 1024, (FEAT_ELEMS + H_ELEMS) * sizeof(float)>>>(
        w1, b1, g1, be1, w2, b2, g2, be2, w3, b3, g3, be3,
        fc1_w, fc1_b, bn1_g, bn1_b, fc2_w, fc2_b, out);
}